// round 4
// baseline (speedup 1.0000x reference)
#include <cuda_runtime.h>
#include <cuda_bf16.h>
#include <math.h>
#include <stdint.h>

// Problem dims
#define BATCH 256
#define TSTEPS 250
#define IDIM 700
#define HDIM 128
#define ODIM 20

// xin buffer: [B][T][H] fp32 = 32.77 MB
__device__ float g_xin[BATCH * TSTEPS * HDIM];

// Correctly-rounded float exp: double exp (<1 ulp in double) rounded once to
// float. Matches glibc expf (correctly rounded) used by a CPU-side reference.
__device__ __forceinline__ float expd(float x)
{
    return (float)exp((double)x);
}

// ---------------------------------------------------------------------------
// Kernel 1: xin[m][h] = (sum_k x[m][k]*w[k][h]) + b[h]  (single fp32 acc,
// ascending k, fmaf, bias added once at the end)
// ---------------------------------------------------------------------------
#define BM 64
#define BK 16

__global__ __launch_bounds__(256) void gemm_xin_kernel(
    const float* __restrict__ X, const float* __restrict__ W,
    const float* __restrict__ bias)
{
    __shared__ float Xs[BK][BM];
    __shared__ float Ws[BK][HDIM];

    const int tid = threadIdx.x;
    const int m0 = blockIdx.x * BM;

    const int ty = tid >> 5;        // 0..7
    const int tx = tid & 31;        // 0..31
    const int mBase = ty * 8;       // 8 rows per thread
    const int nBase = tx * 4;       // 4 cols per thread

    float acc[8][4];
#pragma unroll
    for (int i = 0; i < 8; i++)
#pragma unroll
        for (int j = 0; j < 4; j++) acc[i][j] = 0.f;

    const int lr = tid >> 2;          // 0..63 (X tile row)
    const int lc = (tid & 3) * 4;     // X tile k chunk
    const int wr = tid >> 5;          // 0..7 (W tile row)
    const int wc = (tid & 31) * 4;    // W tile col chunk

    for (int k0 = 0; k0 < IDIM; k0 += BK) {
#pragma unroll
        for (int i = 0; i < 4; i++) {
            int k = k0 + lc + i;
            Xs[lc + i][lr] = (k < IDIM) ? X[(size_t)(m0 + lr) * IDIM + k] : 0.f;
        }
#pragma unroll
        for (int rr = 0; rr < 2; rr++) {
            int k = k0 + wr + rr * 8;
            float4 v = make_float4(0.f, 0.f, 0.f, 0.f);
            if (k < IDIM) v = *(const float4*)&W[(size_t)k * HDIM + wc];
            *(float4*)&Ws[wr + rr * 8][wc] = v;
        }
        __syncthreads();

#pragma unroll
        for (int k = 0; k < BK; k++) {   // strictly ascending k
            float4 x0 = *(float4*)&Xs[k][mBase];
            float4 x1 = *(float4*)&Xs[k][mBase + 4];
            float4 w4 = *(float4*)&Ws[k][nBase];
            float xv[8] = {x0.x, x0.y, x0.z, x0.w, x1.x, x1.y, x1.z, x1.w};
            float wv[4] = {w4.x, w4.y, w4.z, w4.w};
#pragma unroll
            for (int i = 0; i < 8; i++)
#pragma unroll
                for (int j = 0; j < 4; j++)
                    acc[i][j] = fmaf(xv[i], wv[j], acc[i][j]);
        }
        __syncthreads();
    }

    float4 bb = *(const float4*)&bias[nBase];
#pragma unroll
    for (int i = 0; i < 8; i++) {
        float4 r;
        r.x = __fadd_rn(acc[i][0], bb.x);
        r.y = __fadd_rn(acc[i][1], bb.y);
        r.z = __fadd_rn(acc[i][2], bb.z);
        r.w = __fadd_rn(acc[i][3], bb.w);
        *(float4*)&g_xin[(size_t)(m0 + mBase + i) * HDIM + nBase] = r;
    }
}

// ---------------------------------------------------------------------------
// Kernel 2: A_norm = sum|w_h1h1*mask0| + sum|w_h2h2*mask1|   (fp32)
// ---------------------------------------------------------------------------
__global__ void anorm_kernel(const float* __restrict__ w11,
                             const float* __restrict__ w22,
                             const float* __restrict__ mask,
                             float* __restrict__ out)
{
    __shared__ float redA[256];
    __shared__ float redB[256];
    int tid = threadIdx.x;
    float sa = 0.f, sb = 0.f;
    for (int i = tid; i < HDIM * HDIM; i += 256) {
        sa += fabsf(__fmul_rn(w11[i], mask[i]));
        sb += fabsf(__fmul_rn(w22[i], mask[HDIM * HDIM + i]));
    }
    redA[tid] = sa;
    redB[tid] = sb;
    __syncthreads();
    for (int o = 128; o > 0; o >>= 1) {
        if (tid < o) { redA[tid] += redA[tid + o]; redB[tid] += redB[tid + o]; }
        __syncthreads();
    }
    if (tid == 0)
        out[BATCH * ODIM + 2 * BATCH * HDIM] = __fadd_rn(redA[0], redB[0]);
}

// ---------------------------------------------------------------------------
// Kernel 3: persistent scan. grid = 128 blocks x 128 threads.
// Block b owns batch rows {2b, 2b+1}. thread = hidden index h.
// Dots: single fp32 accumulator, ascending j, fmaf, from 0.
// Elementwise: explicit __f*_rn intrinsics. exp: correctly rounded (double).
// ---------------------------------------------------------------------------
__device__ __forceinline__ void dot_pair(const float* __restrict__ W,
                                         const float* __restrict__ sa,
                                         const float* __restrict__ sb,
                                         int h, float& a0, float& a1)
{
#pragma unroll 4
    for (int j = 0; j < HDIM; j += 4) {
        float4 va = *(const float4*)(sa + j);
        float4 vb = *(const float4*)(sb + j);
        if (va.x != 0.f || vb.x != 0.f) {
            float w = W[(j + 0) * HDIM + h];
            a0 = fmaf(va.x, w, a0); a1 = fmaf(vb.x, w, a1);
        }
        if (va.y != 0.f || vb.y != 0.f) {
            float w = W[(j + 1) * HDIM + h];
            a0 = fmaf(va.y, w, a0); a1 = fmaf(vb.y, w, a1);
        }
        if (va.z != 0.f || vb.z != 0.f) {
            float w = W[(j + 2) * HDIM + h];
            a0 = fmaf(va.z, w, a0); a1 = fmaf(vb.z, w, a1);
        }
        if (va.w != 0.f || vb.w != 0.f) {
            float w = W[(j + 3) * HDIM + h];
            a0 = fmaf(va.w, w, a0); a1 = fmaf(vb.w, w, a1);
        }
    }
}

#define SM_W11 0
#define SM_W12 (HDIM * HDIM)
#define SM_W22 (2 * HDIM * HDIM)
#define SM_W2O (3 * HDIM * HDIM)
#define SM_S1  (3 * HDIM * HDIM + HDIM * ODIM)
#define SM_S2  (SM_S1 + 2 * HDIM)
#define SMEM_FLOATS (SM_S2 + 2 * HDIM)

__global__ __launch_bounds__(128) void scan_kernel(
    const float* __restrict__ mask,
    const float* __restrict__ w_h1h1, const float* __restrict__ b_h1h1,
    const float* __restrict__ w_h1h2, const float* __restrict__ b_h1h2,
    const float* __restrict__ w_h2h2, const float* __restrict__ b_h2h2,
    const float* __restrict__ w_h2o,  const float* __restrict__ b_h2o,
    const float* __restrict__ tau_adp_h1, const float* __restrict__ tau_adp_h2,
    const float* __restrict__ tau_m_h1,   const float* __restrict__ tau_m_h2,
    const float* __restrict__ tau_m_o,
    const float* __restrict__ hid1_mem0, const float* __restrict__ hid2_mem0,
    const float* __restrict__ out_mem0,
    float* __restrict__ out)
{
    extern __shared__ float sm[];
    float* w11 = sm + SM_W11;
    float* w12 = sm + SM_W12;
    float* w22 = sm + SM_W22;
    float* w2o = sm + SM_W2O;
    float* s1s = sm + SM_S1;   // [2][128]
    float* s2s = sm + SM_S2;   // [2][128]

    const int h = threadIdx.x;
    const int r0 = blockIdx.x * 2;
    const int r1 = r0 + 1;

    for (int idx = h; idx < HDIM * HDIM; idx += 128) {
        w11[idx] = __fmul_rn(w_h1h1[idx], mask[idx]);
        w12[idx] = w_h1h2[idx];
        w22[idx] = __fmul_rn(w_h2h2[idx], mask[HDIM * HDIM + idx]);
    }
    for (int idx = h; idx < HDIM * ODIM; idx += 128) w2o[idx] = w_h2o[idx];

    // decay constants: exp correctly rounded via double
    const float a1  = expd(__fdiv_rn(-1.0f, tau_m_h1[h]));
    const float r1d = expd(__fdiv_rn(-1.0f, tau_adp_h1[h]));
    const float a2  = expd(__fdiv_rn(-1.0f, tau_m_h2[h]));
    const float r2d = expd(__fdiv_rn(-1.0f, tau_adp_h2[h]));
    const float om_a1  = __fsub_rn(1.0f, a1);
    const float om_r1d = __fsub_rn(1.0f, r1d);
    const float om_a2  = __fsub_rn(1.0f, a2);
    const float om_r2d = __fsub_rn(1.0f, r2d);
    const float bh11 = b_h1h1[h];
    const float b12  = b_h1h2[h];
    const float b22c = b_h2h2[h];

    float h1m0 = hid1_mem0[r0 * HDIM + h], h1m1 = hid1_mem0[r1 * HDIM + h];
    float h2m0 = hid2_mem0[r0 * HDIM + h], h2m1 = hid2_mem0[r1 * HDIM + h];
    float b1_0 = 0.01f, b1_1 = 0.01f, b2_0 = 0.01f, b2_1 = 0.01f;
    float s1reg0 = 0.f, s1reg1 = 0.f, s2reg0 = 0.f, s2reg1 = 0.f;
    float s1c0 = 0.f, s1c1 = 0.f, s2c0 = 0.f, s2c1 = 0.f;

    s1s[h] = 0.f; s1s[HDIM + h] = 0.f;
    s2s[h] = 0.f; s2s[HDIM + h] = 0.f;

    const int warp = h >> 5, lane = h & 31;
    float om = 0.f, accv = 0.f, ao = 0.f, om_ao = 0.f, b2o = 0.f;
    if (warp < 2 && lane < ODIM) {
        om    = out_mem0[(r0 + warp) * ODIM + lane];
        ao    = expd(__fdiv_rn(-1.0f, tau_m_o[lane]));
        om_ao = __fsub_rn(1.0f, ao);
        b2o   = b_h2o[lane];
    }
    __syncthreads();

    float xt0 = g_xin[((size_t)r0 * TSTEPS + 0) * HDIM + h];
    float xt1 = g_xin[((size_t)r1 * TSTEPS + 0) * HDIM + h];

    for (int t = 0; t < TSTEPS; t++) {
        // ---- layer 1 ----
        float d11_0 = 0.f, d11_1 = 0.f;
        dot_pair(w11, s1s, s1s + HDIM, h, d11_0, d11_1);
        float i10 = __fadd_rn(__fadd_rn(xt0, d11_0), bh11);
        float i11 = __fadd_rn(__fadd_rn(xt1, d11_1), bh11);
        if (t < TSTEPS - 1) {
            xt0 = g_xin[((size_t)r0 * TSTEPS + t + 1) * HDIM + h];
            xt1 = g_xin[((size_t)r1 * TSTEPS + t + 1) * HDIM + h];
        }

        b1_0 = __fadd_rn(__fmul_rn(r1d, b1_0), __fmul_rn(om_r1d, s1reg0));
        b1_1 = __fadd_rn(__fmul_rn(r1d, b1_1), __fmul_rn(om_r1d, s1reg1));
        float B10 = __fadd_rn(0.01f, __fmul_rn(1.8f, b1_0));
        float B11 = __fadd_rn(0.01f, __fmul_rn(1.8f, b1_1));
        h1m0 = __fsub_rn(__fadd_rn(__fmul_rn(h1m0, a1), __fmul_rn(om_a1, i10)),
                         __fmul_rn(B10, s1reg0));
        h1m1 = __fsub_rn(__fadd_rn(__fmul_rn(h1m1, a1), __fmul_rn(om_a1, i11)),
                         __fmul_rn(B11, s1reg1));
        float ns0 = __fsub_rn(h1m0, B10) > 0.f ? 1.f : 0.f;
        float ns1 = __fsub_rn(h1m1, B11) > 0.f ? 1.f : 0.f;
        s1c0 += ns0; s1c1 += ns1;

        __syncthreads();
        s1s[h] = ns0; s1s[HDIM + h] = ns1;
        s1reg0 = ns0; s1reg1 = ns1;
        __syncthreads();

        // ---- layer 2: i2 = ((dot12 + b12) + dot22) + b22 ----
        float d12_0 = 0.f, d12_1 = 0.f;
        dot_pair(w12, s1s, s1s + HDIM, h, d12_0, d12_1);
        float d22_0 = 0.f, d22_1 = 0.f;
        dot_pair(w22, s2s, s2s + HDIM, h, d22_0, d22_1);
        float i20 = __fadd_rn(__fadd_rn(__fadd_rn(d12_0, b12), d22_0), b22c);
        float i21 = __fadd_rn(__fadd_rn(__fadd_rn(d12_1, b12), d22_1), b22c);

        b2_0 = __fadd_rn(__fmul_rn(r2d, b2_0), __fmul_rn(om_r2d, s2reg0));
        b2_1 = __fadd_rn(__fmul_rn(r2d, b2_1), __fmul_rn(om_r2d, s2reg1));
        float B20 = __fadd_rn(0.01f, __fmul_rn(1.8f, b2_0));
        float B21 = __fadd_rn(0.01f, __fmul_rn(1.8f, b2_1));
        h2m0 = __fsub_rn(__fadd_rn(__fmul_rn(h2m0, a2), __fmul_rn(om_a2, i20)),
                         __fmul_rn(B20, s2reg0));
        h2m1 = __fsub_rn(__fadd_rn(__fmul_rn(h2m1, a2), __fmul_rn(om_a2, i21)),
                         __fmul_rn(B21, s2reg1));
        float ms0 = __fsub_rn(h2m0, B20) > 0.f ? 1.f : 0.f;
        float ms1 = __fsub_rn(h2m1, B21) > 0.f ? 1.f : 0.f;
        s2c0 += ms0; s2c1 += ms1;

        __syncthreads();
        s2s[h] = ms0; s2s[HDIM + h] = ms1;
        s2reg0 = ms0; s2reg1 = ms1;
        __syncthreads();

        // ---- readout (warp 0 -> row0, warp 1 -> row1) ----
        if (warp < 2) {
            if (lane < ODIM) {
                const float* ss = s2s + warp * HDIM;
                float dio = 0.f;
#pragma unroll 4
                for (int j = 0; j < HDIM; j += 4) {
                    float4 s4 = *(const float4*)(ss + j);
                    if (s4.x != 0.f) dio = __fadd_rn(dio, w2o[(j + 0) * ODIM + lane]);
                    if (s4.y != 0.f) dio = __fadd_rn(dio, w2o[(j + 1) * ODIM + lane]);
                    if (s4.z != 0.f) dio = __fadd_rn(dio, w2o[(j + 2) * ODIM + lane]);
                    if (s4.w != 0.f) dio = __fadd_rn(dio, w2o[(j + 3) * ODIM + lane]);
                }
                float io = __fadd_rn(dio, b2o);
                om = __fadd_rn(__fmul_rn(om, ao), __fmul_rn(om_ao, io));
            }
            // softmax over 20 logits: max and sum strictly ascending (CPU
            // reduce order), exp correctly rounded.
            float v = -3.4e38f;
#pragma unroll
            for (int j = 0; j < ODIM; j++)
                v = fmaxf(v, __shfl_sync(0xffffffffu, om, j));
            float p = (lane < ODIM) ? expd(__fsub_rn(om, v)) : 0.f;
            float ssum = 0.f;
#pragma unroll
            for (int j = 0; j < ODIM; j++)
                ssum = __fadd_rn(ssum, __shfl_sync(0xffffffffu, p, j));
            if (lane < ODIM && t > 10)
                accv = __fadd_rn(accv, __fdiv_rn(p, ssum));
        }
    }

    // ---- outputs: [acc 256x20][s1 256x128][s2 256x128][A_norm] ----
    out[BATCH * ODIM + r0 * HDIM + h] = __fdiv_rn(s1c0, (float)TSTEPS);
    out[BATCH * ODIM + r1 * HDIM + h] = __fdiv_rn(s1c1, (float)TSTEPS);
    out[BATCH * ODIM + BATCH * HDIM + r0 * HDIM + h] = __fdiv_rn(s2c0, (float)TSTEPS);
    out[BATCH * ODIM + BATCH * HDIM + r1 * HDIM + h] = __fdiv_rn(s2c1, (float)TSTEPS);
    if (warp < 2 && lane < ODIM)
        out[(r0 + warp) * ODIM + lane] = accv;
}

// ---------------------------------------------------------------------------
extern "C" void kernel_launch(void* const* d_in, const int* in_sizes, int n_in,
                              void* d_out, int out_size)
{
    const float* x         = (const float*)d_in[0];
    const float* mask      = (const float*)d_in[1];
    const float* w_ih1     = (const float*)d_in[2];
    const float* b_ih1     = (const float*)d_in[3];
    const float* w_h1h1    = (const float*)d_in[4];
    const float* b_h1h1    = (const float*)d_in[5];
    const float* w_h1h2    = (const float*)d_in[6];
    const float* b_h1h2    = (const float*)d_in[7];
    const float* w_h2h2    = (const float*)d_in[8];
    const float* b_h2h2    = (const float*)d_in[9];
    const float* w_h2o     = (const float*)d_in[10];
    const float* b_h2o     = (const float*)d_in[11];
    const float* tau_adp_h1= (const float*)d_in[12];
    const float* tau_adp_h2= (const float*)d_in[13];
    const float* tau_m_h1  = (const float*)d_in[14];
    const float* tau_m_h2  = (const float*)d_in[15];
    const float* tau_m_o   = (const float*)d_in[16];
    const float* hid1_mem0 = (const float*)d_in[17];
    const float* hid2_mem0 = (const float*)d_in[18];
    const float* out_mem0  = (const float*)d_in[19];
    float* out = (float*)d_out;

    gemm_xin_kernel<<<(BATCH * TSTEPS) / BM, 256>>>(x, w_ih1, b_ih1);

    anorm_kernel<<<1, 256>>>(w_h1h1, w_h2h2, mask, out);

    size_t smem = SMEM_FLOATS * sizeof(float);
    cudaFuncSetAttribute(scan_kernel,
                         cudaFuncAttributeMaxDynamicSharedMemorySize,
                         (int)smem);
    scan_kernel<<<BATCH / 2, 128, smem>>>(
        mask, w_h1h1, b_h1h1, w_h1h2, b_h1h2, w_h2h2, b_h2h2,
        w_h2o, b_h2o, tau_adp_h1, tau_adp_h2, tau_m_h1, tau_m_h2,
        tau_m_o, hid1_mem0, hid2_mem0, out_mem0, out);
}

// round 7
// speedup vs baseline: 1.4728x; 1.4728x over previous
#include <cuda_runtime.h>
#include <cuda_bf16.h>
#include <math.h>
#include <stdint.h>

// Problem dims
#define BATCH 256
#define TSTEPS 250
#define IDIM 700
#define HDIM 128
#define ODIM 20

// xin buffer: [B][T][H] fp32 = 32.77 MB
__device__ float g_xin[BATCH * TSTEPS * HDIM];

// Correctly-rounded float exp via double (matches glibc expf).
__device__ __forceinline__ float expd(float x)
{
    return (float)exp((double)x);
}

// ---------------------------------------------------------------------------
// Kernel 1: xin[m][h] = (sum_k x[m][k]*w[k][h]) + b[h]  (single fp32 acc,
// ascending k, fmaf, bias at the end). Double-buffered smem pipeline.
// ---------------------------------------------------------------------------
#define BM 64
#define BK 16

__global__ __launch_bounds__(256) void gemm_xin_kernel(
    const float* __restrict__ X, const float* __restrict__ W,
    const float* __restrict__ bias)
{
    __shared__ float Xs[2][BK][BM];
    __shared__ float Ws[2][BK][HDIM];

    const int tid = threadIdx.x;
    const int m0 = blockIdx.x * BM;

    const int ty = tid >> 5;        // 0..7
    const int tx = tid & 31;        // 0..31
    const int mBase = ty * 8;       // 8 rows per thread
    const int nBase = tx * 4;       // 4 cols per thread

    float acc[8][4];
#pragma unroll
    for (int i = 0; i < 8; i++)
#pragma unroll
        for (int j = 0; j < 4; j++) acc[i][j] = 0.f;

    const int lr = tid >> 2;          // 0..63 (X tile row)
    const int lc = (tid & 3) * 4;     // X tile k chunk
    const int wr = tid >> 5;          // 0..7 (W tile row)
    const int wc = (tid & 31) * 4;    // W tile col chunk

    const int NT = (IDIM + BK - 1) / BK;   // 44

    // prologue: tile 0 straight to smem buffer 0
#pragma unroll
    for (int i = 0; i < 4; i++) {
        int k = lc + i;
        Xs[0][lc + i][lr] = (k < IDIM) ? X[(size_t)(m0 + lr) * IDIM + k] : 0.f;
    }
#pragma unroll
    for (int rr = 0; rr < 2; rr++) {
        int k = wr + rr * 8;
        float4 v = make_float4(0.f, 0.f, 0.f, 0.f);
        if (k < IDIM) v = *(const float4*)&W[(size_t)k * HDIM + wc];
        *(float4*)&Ws[0][wr + rr * 8][wc] = v;
    }
    __syncthreads();

    int buf = 0;
    for (int kt = 0; kt < NT; kt++) {
        const bool has_next = (kt + 1) < NT;
        const int k0n = (kt + 1) * BK;

        // issue next tile's global loads into registers
        float xr[4];
        float4 wv[2];
        if (has_next) {
#pragma unroll
            for (int i = 0; i < 4; i++) {
                int k = k0n + lc + i;
                xr[i] = (k < IDIM) ? X[(size_t)(m0 + lr) * IDIM + k] : 0.f;
            }
#pragma unroll
            for (int rr = 0; rr < 2; rr++) {
                int k = k0n + wr + rr * 8;
                wv[rr] = make_float4(0.f, 0.f, 0.f, 0.f);
                if (k < IDIM) wv[rr] = *(const float4*)&W[(size_t)k * HDIM + wc];
            }
        }

        // compute on current buffer (strictly ascending k)
#pragma unroll
        for (int k = 0; k < BK; k++) {
            float4 x0 = *(float4*)&Xs[buf][k][mBase];
            float4 x1 = *(float4*)&Xs[buf][k][mBase + 4];
            float4 w4 = *(float4*)&Ws[buf][k][nBase];
            float xv[8] = {x0.x, x0.y, x0.z, x0.w, x1.x, x1.y, x1.z, x1.w};
            float wvv[4] = {w4.x, w4.y, w4.z, w4.w};
#pragma unroll
            for (int i = 0; i < 8; i++)
#pragma unroll
                for (int j = 0; j < 4; j++)
                    acc[i][j] = fmaf(xv[i], wvv[j], acc[i][j]);
        }

        if (has_next) {
            int nb = buf ^ 1;
#pragma unroll
            for (int i = 0; i < 4; i++) Xs[nb][lc + i][lr] = xr[i];
#pragma unroll
            for (int rr = 0; rr < 2; rr++)
                *(float4*)&Ws[nb][wr + rr * 8][wc] = wv[rr];
            __syncthreads();
            buf = nb;
        }
    }

    float4 bb = *(const float4*)&bias[nBase];
#pragma unroll
    for (int i = 0; i < 8; i++) {
        float4 r;
        r.x = __fadd_rn(acc[i][0], bb.x);
        r.y = __fadd_rn(acc[i][1], bb.y);
        r.z = __fadd_rn(acc[i][2], bb.z);
        r.w = __fadd_rn(acc[i][3], bb.w);
        *(float4*)&g_xin[(size_t)(m0 + mBase + i) * HDIM + nBase] = r;
    }
}

// ---------------------------------------------------------------------------
// Kernel 2: A_norm
// ---------------------------------------------------------------------------
__global__ void anorm_kernel(const float* __restrict__ w11,
                             const float* __restrict__ w22,
                             const float* __restrict__ mask,
                             float* __restrict__ out)
{
    __shared__ float redA[256];
    __shared__ float redB[256];
    int tid = threadIdx.x;
    float sa = 0.f, sb = 0.f;
    for (int i = tid; i < HDIM * HDIM; i += 256) {
        sa += fabsf(__fmul_rn(w11[i], mask[i]));
        sb += fabsf(__fmul_rn(w22[i], mask[HDIM * HDIM + i]));
    }
    redA[tid] = sa;
    redB[tid] = sb;
    __syncthreads();
    for (int o = 128; o > 0; o >>= 1) {
        if (tid < o) { redA[tid] += redA[tid + o]; redB[tid] += redB[tid + o]; }
        __syncthreads();
    }
    if (tid == 0)
        out[BATCH * ODIM + 2 * BATCH * HDIM] = __fadd_rn(redA[0], redB[0]);
}

// ---------------------------------------------------------------------------
// Kernel 3: persistent scan. grid = 128 blocks x 128 threads.
// Block b owns batch rows {2b, 2b+1}; thread = hidden index h.
// DENSE branch-free dots (fma with 0/1 spike == bit-exact vs skip).
// Double-buffered spike arrays -> 2 barriers per step.
// ---------------------------------------------------------------------------
__device__ __forceinline__ void dot_pair(const float* __restrict__ W,
                                         const float* __restrict__ sa,
                                         const float* __restrict__ sb,
                                         int h, float& a0, float& a1)
{
#pragma unroll 8
    for (int j = 0; j < HDIM; j += 4) {
        float4 va = *(const float4*)(sa + j);
        float4 vb = *(const float4*)(sb + j);
        float w0 = W[(j + 0) * HDIM + h];
        float w1 = W[(j + 1) * HDIM + h];
        float w2 = W[(j + 2) * HDIM + h];
        float w3 = W[(j + 3) * HDIM + h];
        a0 = fmaf(va.x, w0, a0); a1 = fmaf(vb.x, w0, a1);
        a0 = fmaf(va.y, w1, a0); a1 = fmaf(vb.y, w1, a1);
        a0 = fmaf(va.z, w2, a0); a1 = fmaf(vb.z, w2, a1);
        a0 = fmaf(va.w, w3, a0); a1 = fmaf(vb.w, w3, a1);
    }
}

#define SM_W11 0
#define SM_W12 (HDIM * HDIM)
#define SM_W22 (2 * HDIM * HDIM)
#define SM_W2O (3 * HDIM * HDIM)
#define SM_S1  (3 * HDIM * HDIM + HDIM * ODIM)   // [2 phase][2 row][128]
#define SM_S2  (SM_S1 + 4 * HDIM)                // [2 phase][2 row][128]
#define SMEM_FLOATS (SM_S2 + 4 * HDIM)

__global__ __launch_bounds__(128) void scan_kernel(
    const float* __restrict__ mask,
    const float* __restrict__ w_h1h1, const float* __restrict__ b_h1h1,
    const float* __restrict__ w_h1h2, const float* __restrict__ b_h1h2,
    const float* __restrict__ w_h2h2, const float* __restrict__ b_h2h2,
    const float* __restrict__ w_h2o,  const float* __restrict__ b_h2o,
    const float* __restrict__ tau_adp_h1, const float* __restrict__ tau_adp_h2,
    const float* __restrict__ tau_m_h1,   const float* __restrict__ tau_m_h2,
    const float* __restrict__ tau_m_o,
    const float* __restrict__ hid1_mem0, const float* __restrict__ hid2_mem0,
    const float* __restrict__ out_mem0,
    float* __restrict__ out)
{
    extern __shared__ float sm[];
    float* w11 = sm + SM_W11;
    float* w12 = sm + SM_W12;
    float* w22 = sm + SM_W22;
    float* w2o = sm + SM_W2O;
    float* s1b = sm + SM_S1;   // [phase][row][128]
    float* s2b = sm + SM_S2;

    const int h = threadIdx.x;
    const int r0 = blockIdx.x * 2;
    const int r1 = r0 + 1;

    for (int idx = h; idx < HDIM * HDIM; idx += 128) {
        w11[idx] = __fmul_rn(w_h1h1[idx], mask[idx]);
        w12[idx] = w_h1h2[idx];
        w22[idx] = __fmul_rn(w_h2h2[idx], mask[HDIM * HDIM + idx]);
    }
    for (int idx = h; idx < HDIM * ODIM; idx += 128) w2o[idx] = w_h2o[idx];

    const float a1  = expd(__fdiv_rn(-1.0f, tau_m_h1[h]));
    const float r1d = expd(__fdiv_rn(-1.0f, tau_adp_h1[h]));
    const float a2  = expd(__fdiv_rn(-1.0f, tau_m_h2[h]));
    const float r2d = expd(__fdiv_rn(-1.0f, tau_adp_h2[h]));
    const float om_a1  = __fsub_rn(1.0f, a1);
    const float om_r1d = __fsub_rn(1.0f, r1d);
    const float om_a2  = __fsub_rn(1.0f, a2);
    const float om_r2d = __fsub_rn(1.0f, r2d);
    const float bh11 = b_h1h1[h];
    const float b12  = b_h1h2[h];
    const float b22c = b_h2h2[h];

    float h1m0 = hid1_mem0[r0 * HDIM + h], h1m1 = hid1_mem0[r1 * HDIM + h];
    float h2m0 = hid2_mem0[r0 * HDIM + h], h2m1 = hid2_mem0[r1 * HDIM + h];
    float b1_0 = 0.01f, b1_1 = 0.01f, b2_0 = 0.01f, b2_1 = 0.01f;
    float s1reg0 = 0.f, s1reg1 = 0.f, s2reg0 = 0.f, s2reg1 = 0.f;
    float s1c0 = 0.f, s1c1 = 0.f, s2c0 = 0.f, s2c1 = 0.f;

    // zero phase-0 spike buffers (read at t=0)
    s1b[h] = 0.f; s1b[HDIM + h] = 0.f;
    s2b[h] = 0.f; s2b[HDIM + h] = 0.f;

    const int warp = h >> 5, lane = h & 31;
    float om = 0.f, accv = 0.f, ao = 0.f, om_ao = 0.f, b2o = 0.f;
    if (warp < 2 && lane < ODIM) {
        om    = out_mem0[(r0 + warp) * ODIM + lane];
        ao    = expd(__fdiv_rn(-1.0f, tau_m_o[lane]));
        om_ao = __fsub_rn(1.0f, ao);
        b2o   = b_h2o[lane];
    }
    __syncthreads();

    float xt0 = g_xin[((size_t)r0 * TSTEPS + 0) * HDIM + h];
    float xt1 = g_xin[((size_t)r1 * TSTEPS + 0) * HDIM + h];

    for (int t = 0; t < TSTEPS; t++) {
        const int rd = (t & 1) * 2 * HDIM;      // phase offset to read
        const int wr = ((t & 1) ^ 1) * 2 * HDIM; // phase offset to write

        // ---- layer 1: dot over previous s1 spikes ----
        float d11_0 = 0.f, d11_1 = 0.f;
        dot_pair(w11, s1b + rd, s1b + rd + HDIM, h, d11_0, d11_1);
        float i10 = __fadd_rn(__fadd_rn(xt0, d11_0), bh11);
        float i11 = __fadd_rn(__fadd_rn(xt1, d11_1), bh11);
        if (t < TSTEPS - 1) {
            xt0 = g_xin[((size_t)r0 * TSTEPS + t + 1) * HDIM + h];
            xt1 = g_xin[((size_t)r1 * TSTEPS + t + 1) * HDIM + h];
        }

        b1_0 = __fadd_rn(__fmul_rn(r1d, b1_0), __fmul_rn(om_r1d, s1reg0));
        b1_1 = __fadd_rn(__fmul_rn(r1d, b1_1), __fmul_rn(om_r1d, s1reg1));
        float B10 = __fadd_rn(0.01f, __fmul_rn(1.8f, b1_0));
        float B11 = __fadd_rn(0.01f, __fmul_rn(1.8f, b1_1));
        h1m0 = __fsub_rn(__fadd_rn(__fmul_rn(h1m0, a1), __fmul_rn(om_a1, i10)),
                         __fmul_rn(B10, s1reg0));
        h1m1 = __fsub_rn(__fadd_rn(__fmul_rn(h1m1, a1), __fmul_rn(om_a1, i11)),
                         __fmul_rn(B11, s1reg1));
        float ns0 = __fsub_rn(h1m0, B10) > 0.f ? 1.f : 0.f;
        float ns1 = __fsub_rn(h1m1, B11) > 0.f ? 1.f : 0.f;
        s1c0 += ns0; s1c1 += ns1;

        s1b[wr + h] = ns0; s1b[wr + HDIM + h] = ns1;
        s1reg0 = ns0; s1reg1 = ns1;
        __syncthreads();                         // sync 1: new s1 visible

        // ---- layer 2: dot12 over NEW s1 (wr), dot22 over OLD s2 (rd) ----
        float d12_0 = 0.f, d12_1 = 0.f;
        dot_pair(w12, s1b + wr, s1b + wr + HDIM, h, d12_0, d12_1);
        float d22_0 = 0.f, d22_1 = 0.f;
        dot_pair(w22, s2b + rd, s2b + rd + HDIM, h, d22_0, d22_1);
        float i20 = __fadd_rn(__fadd_rn(__fadd_rn(d12_0, b12), d22_0), b22c);
        float i21 = __fadd_rn(__fadd_rn(__fadd_rn(d12_1, b12), d22_1), b22c);

        b2_0 = __fadd_rn(__fmul_rn(r2d, b2_0), __fmul_rn(om_r2d, s2reg0));
        b2_1 = __fadd_rn(__fmul_rn(r2d, b2_1), __fmul_rn(om_r2d, s2reg1));
        float B20 = __fadd_rn(0.01f, __fmul_rn(1.8f, b2_0));
        float B21 = __fadd_rn(0.01f, __fmul_rn(1.8f, b2_1));
        h2m0 = __fsub_rn(__fadd_rn(__fmul_rn(h2m0, a2), __fmul_rn(om_a2, i20)),
                         __fmul_rn(B20, s2reg0));
        h2m1 = __fsub_rn(__fadd_rn(__fmul_rn(h2m1, a2), __fmul_rn(om_a2, i21)),
                         __fmul_rn(B21, s2reg1));
        float ms0 = __fsub_rn(h2m0, B20) > 0.f ? 1.f : 0.f;
        float ms1 = __fsub_rn(h2m1, B21) > 0.f ? 1.f : 0.f;
        s2c0 += ms0; s2c1 += ms1;

        s2b[wr + h] = ms0; s2b[wr + HDIM + h] = ms1;
        s2reg0 = ms0; s2reg1 = ms1;
        __syncthreads();                         // sync 2: new s2 visible

        // ---- readout (warp 0 -> row0, warp 1 -> row1), dense fma ----
        if (warp < 2) {
            if (lane < ODIM) {
                const float* ss = s2b + wr + warp * HDIM;
                float dio = 0.f;
#pragma unroll 4
                for (int j = 0; j < HDIM; j++)
                    dio = fmaf(ss[j], w2o[j * ODIM + lane], dio);
                float io = __fadd_rn(dio, b2o);
                om = __fadd_rn(__fmul_rn(om, ao), __fmul_rn(om_ao, io));
            }
            // softmax over 20 logits: strictly ascending max and sum
            float v = -3.4e38f;
#pragma unroll
            for (int j = 0; j < ODIM; j++)
                v = fmaxf(v, __shfl_sync(0xffffffffu, om, j));
            float p = (lane < ODIM) ? expd(__fsub_rn(om, v)) : 0.f;
            float ssum = 0.f;
#pragma unroll
            for (int j = 0; j < ODIM; j++)
                ssum = __fadd_rn(ssum, __shfl_sync(0xffffffffu, p, j));
            if (lane < ODIM && t > 10)
                accv = __fadd_rn(accv, __fdiv_rn(p, ssum));
        }
    }

    // ---- outputs: [acc 256x20][s1 256x128][s2 256x128][A_norm] ----
    out[BATCH * ODIM + r0 * HDIM + h] = __fdiv_rn(s1c0, (float)TSTEPS);
    out[BATCH * ODIM + r1 * HDIM + h] = __fdiv_rn(s1c1, (float)TSTEPS);
    out[BATCH * ODIM + BATCH * HDIM + r0 * HDIM + h] = __fdiv_rn(s2c0, (float)TSTEPS);
    out[BATCH * ODIM + BATCH * HDIM + r1 * HDIM + h] = __fdiv_rn(s2c1, (float)TSTEPS);
    if (warp < 2 && lane < ODIM)
        out[(r0 + warp) * ODIM + lane] = accv;
}

// ---------------------------------------------------------------------------
extern "C" void kernel_launch(void* const* d_in, const int* in_sizes, int n_in,
                              void* d_out, int out_size)
{
    const float* x         = (const float*)d_in[0];
    const float* mask      = (const float*)d_in[1];
    const float* w_ih1     = (const float*)d_in[2];
    const float* b_ih1     = (const float*)d_in[3];
    const float* w_h1h1    = (const float*)d_in[4];
    const float* b_h1h1    = (const float*)d_in[5];
    const float* w_h1h2    = (const float*)d_in[6];
    const float* b_h1h2    = (const float*)d_in[7];
    const float* w_h2h2    = (const float*)d_in[8];
    const float* b_h2h2    = (const float*)d_in[9];
    const float* w_h2o     = (const float*)d_in[10];
    const float* b_h2o     = (const float*)d_in[11];
    const float* tau_adp_h1= (const float*)d_in[12];
    const float* tau_adp_h2= (const float*)d_in[13];
    const float* tau_m_h1  = (const float*)d_in[14];
    const float* tau_m_h2  = (const float*)d_in[15];
    const float* tau_m_o   = (const float*)d_in[16];
    const float* hid1_mem0 = (const float*)d_in[17];
    const float* hid2_mem0 = (const float*)d_in[18];
    const float* out_mem0  = (const float*)d_in[19];
    float* out = (float*)d_out;

    gemm_xin_kernel<<<(BATCH * TSTEPS) / BM, 256>>>(x, w_ih1, b_ih1);

    anorm_kernel<<<1, 256>>>(w_h1h1, w_h2h2, mask, out);

    size_t smem = SMEM_FLOATS * sizeof(float);
    cudaFuncSetAttribute(scan_kernel,
                         cudaFuncAttributeMaxDynamicSharedMemorySize,
                         (int)smem);
    scan_kernel<<<BATCH / 2, 128, smem>>>(
        mask, w_h1h1, b_h1h1, w_h1h2, b_h1h2, w_h2h2, b_h2h2,
        w_h2o, b_h2o, tau_adp_h1, tau_adp_h2, tau_m_h1, tau_m_h2,
        tau_m_o, hid1_mem0, hid2_mem0, out_mem0, out);
}

// round 9
// speedup vs baseline: 2.1877x; 1.4854x over previous
#include <cuda_runtime.h>
#include <cuda_bf16.h>
#include <math.h>
#include <stdint.h>

// Problem dims
#define BATCH 256
#define TSTEPS 250
#define IDIM 700
#define HDIM 128
#define ODIM 20

// xin buffer: [B][T][H] fp32 = 32.77 MB
__device__ float g_xin[BATCH * TSTEPS * HDIM];

// Correctly-rounded float exp via double (matches glibc expf). Init-path only.
__device__ __forceinline__ float expd(float x)
{
    return (float)exp((double)x);
}

#define BARSYNC(id, cnt) asm volatile("bar.sync %0, %1;" :: "r"(id), "r"(cnt) : "memory")

// ---------------------------------------------------------------------------
// Kernel 1: xin[m][h] = (sum_k x[m][k]*w[k][h]) + b[h]  (single fp32 acc,
// ascending k, fmaf, bias at the end). Double-buffered smem pipeline.
// ---------------------------------------------------------------------------
#define BM 64
#define BK 16

__global__ __launch_bounds__(256) void gemm_xin_kernel(
    const float* __restrict__ X, const float* __restrict__ W,
    const float* __restrict__ bias)
{
    __shared__ float Xs[2][BK][BM];
    __shared__ float Ws[2][BK][HDIM];

    const int tid = threadIdx.x;
    const int m0 = blockIdx.x * BM;

    const int ty = tid >> 5;        // 0..7
    const int tx = tid & 31;        // 0..31
    const int mBase = ty * 8;       // 8 rows per thread
    const int nBase = tx * 4;       // 4 cols per thread

    float acc[8][4];
#pragma unroll
    for (int i = 0; i < 8; i++)
#pragma unroll
        for (int j = 0; j < 4; j++) acc[i][j] = 0.f;

    const int lr = tid >> 2;          // 0..63 (X tile row)
    const int lc = (tid & 3) * 4;     // X tile k chunk
    const int wr = tid >> 5;          // 0..7 (W tile row)
    const int wc = (tid & 31) * 4;    // W tile col chunk

    const int NT = (IDIM + BK - 1) / BK;   // 44

#pragma unroll
    for (int i = 0; i < 4; i++) {
        int k = lc + i;
        Xs[0][lc + i][lr] = (k < IDIM) ? X[(size_t)(m0 + lr) * IDIM + k] : 0.f;
    }
#pragma unroll
    for (int rr = 0; rr < 2; rr++) {
        int k = wr + rr * 8;
        float4 v = make_float4(0.f, 0.f, 0.f, 0.f);
        if (k < IDIM) v = *(const float4*)&W[(size_t)k * HDIM + wc];
        *(float4*)&Ws[0][wr + rr * 8][wc] = v;
    }
    __syncthreads();

    int buf = 0;
    for (int kt = 0; kt < NT; kt++) {
        const bool has_next = (kt + 1) < NT;
        const int k0n = (kt + 1) * BK;

        float xr[4];
        float4 wv[2];
        if (has_next) {
#pragma unroll
            for (int i = 0; i < 4; i++) {
                int k = k0n + lc + i;
                xr[i] = (k < IDIM) ? X[(size_t)(m0 + lr) * IDIM + k] : 0.f;
            }
#pragma unroll
            for (int rr = 0; rr < 2; rr++) {
                int k = k0n + wr + rr * 8;
                wv[rr] = make_float4(0.f, 0.f, 0.f, 0.f);
                if (k < IDIM) wv[rr] = *(const float4*)&W[(size_t)k * HDIM + wc];
            }
        }

#pragma unroll
        for (int k = 0; k < BK; k++) {   // strictly ascending k
            float4 x0 = *(float4*)&Xs[buf][k][mBase];
            float4 x1 = *(float4*)&Xs[buf][k][mBase + 4];
            float4 w4 = *(float4*)&Ws[buf][k][nBase];
            float xv[8] = {x0.x, x0.y, x0.z, x0.w, x1.x, x1.y, x1.z, x1.w};
            float wvv[4] = {w4.x, w4.y, w4.z, w4.w};
#pragma unroll
            for (int i = 0; i < 8; i++)
#pragma unroll
                for (int j = 0; j < 4; j++)
                    acc[i][j] = fmaf(xv[i], wvv[j], acc[i][j]);
        }

        if (has_next) {
            int nb = buf ^ 1;
#pragma unroll
            for (int i = 0; i < 4; i++) Xs[nb][lc + i][lr] = xr[i];
#pragma unroll
            for (int rr = 0; rr < 2; rr++)
                *(float4*)&Ws[nb][wr + rr * 8][wc] = wv[rr];
            __syncthreads();
            buf = nb;
        }
    }

    float4 bb = *(const float4*)&bias[nBase];
#pragma unroll
    for (int i = 0; i < 8; i++) {
        float4 r;
        r.x = __fadd_rn(acc[i][0], bb.x);
        r.y = __fadd_rn(acc[i][1], bb.y);
        r.z = __fadd_rn(acc[i][2], bb.z);
        r.w = __fadd_rn(acc[i][3], bb.w);
        *(float4*)&g_xin[(size_t)(m0 + mBase + i) * HDIM + nBase] = r;
    }
}

// ---------------------------------------------------------------------------
// Kernel 2: A_norm
// ---------------------------------------------------------------------------
__global__ void anorm_kernel(const float* __restrict__ w11,
                             const float* __restrict__ w22,
                             const float* __restrict__ mask,
                             float* __restrict__ out)
{
    __shared__ float redA[256];
    __shared__ float redB[256];
    int tid = threadIdx.x;
    float sa = 0.f, sb = 0.f;
    for (int i = tid; i < HDIM * HDIM; i += 256) {
        sa += fabsf(__fmul_rn(w11[i], mask[i]));
        sb += fabsf(__fmul_rn(w22[i], mask[HDIM * HDIM + i]));
    }
    redA[tid] = sa;
    redB[tid] = sb;
    __syncthreads();
    for (int o = 128; o > 0; o >>= 1) {
        if (tid < o) { redA[tid] += redA[tid + o]; redB[tid] += redB[tid + o]; }
        __syncthreads();
    }
    if (tid == 0)
        out[BATCH * ODIM + 2 * BATCH * HDIM] = __fadd_rn(redA[0], redB[0]);
}

// ---------------------------------------------------------------------------
// Kernel 3: persistent scan. grid = 128 blocks x 192 threads.
// Warps 0-3 (128 thr): neuron compute, thread = hidden index h, 2 batch rows.
// Warps 4-5: pipelined readout+softmax, one per row, running 1 step behind
// on the double-buffered s2 phase arrays (a full step of slack before WAR).
// Barriers: id1 cnt128 (compute mid-step), id2 cnt192 (step end / handoff).
// ---------------------------------------------------------------------------
__device__ __forceinline__ void dot_pair(const float* __restrict__ W,
                                         const float* __restrict__ sa,
                                         const float* __restrict__ sb,
                                         int h, float& a0, float& a1)
{
#pragma unroll 8
    for (int j = 0; j < HDIM; j += 4) {
        float4 va = *(const float4*)(sa + j);
        float4 vb = *(const float4*)(sb + j);
        float w0 = W[(j + 0) * HDIM + h];
        float w1 = W[(j + 1) * HDIM + h];
        float w2 = W[(j + 2) * HDIM + h];
        float w3 = W[(j + 3) * HDIM + h];
        a0 = fmaf(va.x, w0, a0); a1 = fmaf(vb.x, w0, a1);
        a0 = fmaf(va.y, w1, a0); a1 = fmaf(vb.y, w1, a1);
        a0 = fmaf(va.z, w2, a0); a1 = fmaf(vb.z, w2, a1);
        a0 = fmaf(va.w, w3, a0); a1 = fmaf(vb.w, w3, a1);
    }
}

#define SM_W11 0
#define SM_W12 (HDIM * HDIM)
#define SM_W22 (2 * HDIM * HDIM)
#define SM_W2O (3 * HDIM * HDIM)
#define SM_S1  (3 * HDIM * HDIM + HDIM * ODIM)   // [2 phase][2 row][128]
#define SM_S2  (SM_S1 + 4 * HDIM)                // [2 phase][2 row][128]
#define SMEM_FLOATS (SM_S2 + 4 * HDIM)

#define NTHREADS_SCAN 192

__global__ __launch_bounds__(NTHREADS_SCAN) void scan_kernel(
    const float* __restrict__ mask,
    const float* __restrict__ w_h1h1, const float* __restrict__ b_h1h1,
    const float* __restrict__ w_h1h2, const float* __restrict__ b_h1h2,
    const float* __restrict__ w_h2h2, const float* __restrict__ b_h2h2,
    const float* __restrict__ w_h2o,  const float* __restrict__ b_h2o,
    const float* __restrict__ tau_adp_h1, const float* __restrict__ tau_adp_h2,
    const float* __restrict__ tau_m_h1,   const float* __restrict__ tau_m_h2,
    const float* __restrict__ tau_m_o,
    const float* __restrict__ hid1_mem0, const float* __restrict__ hid2_mem0,
    const float* __restrict__ out_mem0,
    float* __restrict__ out)
{
    extern __shared__ float sm[];
    float* w11 = sm + SM_W11;
    float* w12 = sm + SM_W12;
    float* w22 = sm + SM_W22;
    float* w2o = sm + SM_W2O;
    float* s1b = sm + SM_S1;   // [phase][row][128]
    float* s2b = sm + SM_S2;

    const int tid = threadIdx.x;
    const int r0 = blockIdx.x * 2;
    const int r1 = r0 + 1;

    // cooperative weight load (all 192 threads)
    for (int idx = tid; idx < HDIM * HDIM; idx += NTHREADS_SCAN) {
        w11[idx] = __fmul_rn(w_h1h1[idx], mask[idx]);
        w12[idx] = w_h1h2[idx];
        w22[idx] = __fmul_rn(w_h2h2[idx], mask[HDIM * HDIM + idx]);
    }
    for (int idx = tid; idx < HDIM * ODIM; idx += NTHREADS_SCAN)
        w2o[idx] = w_h2o[idx];

    if (tid < 128) {
        // ================= compute warps (0-3) =================
        const int h = tid;

        const float a1  = expd(__fdiv_rn(-1.0f, tau_m_h1[h]));
        const float r1d = expd(__fdiv_rn(-1.0f, tau_adp_h1[h]));
        const float a2  = expd(__fdiv_rn(-1.0f, tau_m_h2[h]));
        const float r2d = expd(__fdiv_rn(-1.0f, tau_adp_h2[h]));
        const float om_a1  = __fsub_rn(1.0f, a1);
        const float om_r1d = __fsub_rn(1.0f, r1d);
        const float om_a2  = __fsub_rn(1.0f, a2);
        const float om_r2d = __fsub_rn(1.0f, r2d);
        const float bh11 = b_h1h1[h];
        const float b12  = b_h1h2[h];
        const float b22c = b_h2h2[h];

        float h1m0 = hid1_mem0[r0 * HDIM + h], h1m1 = hid1_mem0[r1 * HDIM + h];
        float h2m0 = hid2_mem0[r0 * HDIM + h], h2m1 = hid2_mem0[r1 * HDIM + h];
        float b1_0 = 0.01f, b1_1 = 0.01f, b2_0 = 0.01f, b2_1 = 0.01f;
        float s1reg0 = 0.f, s1reg1 = 0.f, s2reg0 = 0.f, s2reg1 = 0.f;
        float s1c0 = 0.f, s1c1 = 0.f, s2c0 = 0.f, s2c1 = 0.f;

        // zero phase-0 spike buffers (read at t=0)
        s1b[h] = 0.f; s1b[HDIM + h] = 0.f;
        s2b[h] = 0.f; s2b[HDIM + h] = 0.f;

        __syncthreads();

        float xt0 = g_xin[((size_t)r0 * TSTEPS + 0) * HDIM + h];
        float xt1 = g_xin[((size_t)r1 * TSTEPS + 0) * HDIM + h];

        for (int t = 0; t < TSTEPS; t++) {
            const int rd = (t & 1) * 2 * HDIM;
            const int wr = ((t & 1) ^ 1) * 2 * HDIM;

            // ---- layer 1 ----
            float d11_0 = 0.f, d11_1 = 0.f;
            dot_pair(w11, s1b + rd, s1b + rd + HDIM, h, d11_0, d11_1);
            float i10 = __fadd_rn(__fadd_rn(xt0, d11_0), bh11);
            float i11 = __fadd_rn(__fadd_rn(xt1, d11_1), bh11);
            if (t < TSTEPS - 1) {
                xt0 = g_xin[((size_t)r0 * TSTEPS + t + 1) * HDIM + h];
                xt1 = g_xin[((size_t)r1 * TSTEPS + t + 1) * HDIM + h];
            }

            b1_0 = __fadd_rn(__fmul_rn(r1d, b1_0), __fmul_rn(om_r1d, s1reg0));
            b1_1 = __fadd_rn(__fmul_rn(r1d, b1_1), __fmul_rn(om_r1d, s1reg1));
            float B10 = __fadd_rn(0.01f, __fmul_rn(1.8f, b1_0));
            float B11 = __fadd_rn(0.01f, __fmul_rn(1.8f, b1_1));
            h1m0 = __fsub_rn(__fadd_rn(__fmul_rn(h1m0, a1), __fmul_rn(om_a1, i10)),
                             __fmul_rn(B10, s1reg0));
            h1m1 = __fsub_rn(__fadd_rn(__fmul_rn(h1m1, a1), __fmul_rn(om_a1, i11)),
                             __fmul_rn(B11, s1reg1));
            float ns0 = __fsub_rn(h1m0, B10) > 0.f ? 1.f : 0.f;
            float ns1 = __fsub_rn(h1m1, B11) > 0.f ? 1.f : 0.f;
            s1c0 += ns0; s1c1 += ns1;

            s1b[wr + h] = ns0; s1b[wr + HDIM + h] = ns1;
            s1reg0 = ns0; s1reg1 = ns1;
            BARSYNC(1, 128);                     // new s1 visible (compute only)

            // ---- layer 2 ----
            float d12_0 = 0.f, d12_1 = 0.f;
            dot_pair(w12, s1b + wr, s1b + wr + HDIM, h, d12_0, d12_1);
            float d22_0 = 0.f, d22_1 = 0.f;
            dot_pair(w22, s2b + rd, s2b + rd + HDIM, h, d22_0, d22_1);
            float i20 = __fadd_rn(__fadd_rn(__fadd_rn(d12_0, b12), d22_0), b22c);
            float i21 = __fadd_rn(__fadd_rn(__fadd_rn(d12_1, b12), d22_1), b22c);

            b2_0 = __fadd_rn(__fmul_rn(r2d, b2_0), __fmul_rn(om_r2d, s2reg0));
            b2_1 = __fadd_rn(__fmul_rn(r2d, b2_1), __fmul_rn(om_r2d, s2reg1));
            float B20 = __fadd_rn(0.01f, __fmul_rn(1.8f, b2_0));
            float B21 = __fadd_rn(0.01f, __fmul_rn(1.8f, b2_1));
            h2m0 = __fsub_rn(__fadd_rn(__fmul_rn(h2m0, a2), __fmul_rn(om_a2, i20)),
                             __fmul_rn(B20, s2reg0));
            h2m1 = __fsub_rn(__fadd_rn(__fmul_rn(h2m1, a2), __fmul_rn(om_a2, i21)),
                             __fmul_rn(B21, s2reg1));
            float ms0 = __fsub_rn(h2m0, B20) > 0.f ? 1.f : 0.f;
            float ms1 = __fsub_rn(h2m1, B21) > 0.f ? 1.f : 0.f;
            s2c0 += ms0; s2c1 += ms1;

            s2b[wr + h] = ms0; s2b[wr + HDIM + h] = ms1;
            s2reg0 = ms0; s2reg1 = ms1;
            BARSYNC(2, 192);                     // step end: hand s2 to readout
        }

        out[BATCH * ODIM + r0 * HDIM + h] = __fdiv_rn(s1c0, (float)TSTEPS);
        out[BATCH * ODIM + r1 * HDIM + h] = __fdiv_rn(s1c1, (float)TSTEPS);
        out[BATCH * ODIM + BATCH * HDIM + r0 * HDIM + h] = __fdiv_rn(s2c0, (float)TSTEPS);
        out[BATCH * ODIM + BATCH * HDIM + r1 * HDIM + h] = __fdiv_rn(s2c1, (float)TSTEPS);
    } else {
        // ================= readout warps (4-5), one per row =================
        const int lane = tid & 31;
        const int row  = (tid >> 5) - 4;         // 0 or 1

        float om = 0.f, accv = 0.f, ao = 0.f, om_ao = 0.f, b2o = 0.f;
        if (lane < ODIM) {
            om    = out_mem0[(r0 + row) * ODIM + lane];
            ao    = expd(__fdiv_rn(-1.0f, tau_m_o[lane]));
            om_ao = __fsub_rn(1.0f, ao);
            b2o   = b_h2o[lane];
        }
        __syncthreads();

        for (int t = 0; t < TSTEPS; t++) {
            BARSYNC(2, 192);                     // s2 of step t is ready
            const int wr = ((t & 1) ^ 1) * 2 * HDIM;
            const float* ss = s2b + wr + row * HDIM;

            if (lane < ODIM) {
                float dio = 0.f;                 // ascending j, single acc
#pragma unroll 4
                for (int j = 0; j < HDIM; j++)
                    dio = fmaf(ss[j], w2o[j * ODIM + lane], dio);
                float io = __fadd_rn(dio, b2o);
                om = __fadd_rn(__fmul_rn(om, ao), __fmul_rn(om_ao, io));
            }
            // softmax over 20 logits: tree max (exact) + tree sum (ulp noise
            // on output 0 only; no trajectory feedback) + float expf.
            float v = (lane < ODIM) ? om : -3.4e38f;
#pragma unroll
            for (int off = 16; off > 0; off >>= 1)
                v = fmaxf(v, __shfl_xor_sync(0xffffffffu, v, off));
            float p = (lane < ODIM) ? expf(__fsub_rn(om, v)) : 0.f;
            float ssum = p;
#pragma unroll
            for (int off = 16; off > 0; off >>= 1)
                ssum = __fadd_rn(ssum, __shfl_xor_sync(0xffffffffu, ssum, off));
            if (lane < ODIM && t > 10)
                accv = __fadd_rn(accv, __fdiv_rn(p, ssum));
        }

        if (lane < ODIM)
            out[(r0 + row) * ODIM + lane] = accv;
    }
}

// ---------------------------------------------------------------------------
extern "C" void kernel_launch(void* const* d_in, const int* in_sizes, int n_in,
                              void* d_out, int out_size)
{
    const float* x         = (const float*)d_in[0];
    const float* mask      = (const float*)d_in[1];
    const float* w_ih1     = (const float*)d_in[2];
    const float* b_ih1     = (const float*)d_in[3];
    const float* w_h1h1    = (const float*)d_in[4];
    const float* b_h1h1    = (const float*)d_in[5];
    const float* w_h1h2    = (const float*)d_in[6];
    const float* b_h1h2    = (const float*)d_in[7];
    const float* w_h2h2    = (const float*)d_in[8];
    const float* b_h2h2    = (const float*)d_in[9];
    const float* w_h2o     = (const float*)d_in[10];
    const float* b_h2o     = (const float*)d_in[11];
    const float* tau_adp_h1= (const float*)d_in[12];
    const float* tau_adp_h2= (const float*)d_in[13];
    const float* tau_m_h1  = (const float*)d_in[14];
    const float* tau_m_h2  = (const float*)d_in[15];
    const float* tau_m_o   = (const float*)d_in[16];
    const float* hid1_mem0 = (const float*)d_in[17];
    const float* hid2_mem0 = (const float*)d_in[18];
    const float* out_mem0  = (const float*)d_in[19];
    float* out = (float*)d_out;

    gemm_xin_kernel<<<(BATCH * TSTEPS) / BM, 256>>>(x, w_ih1, b_ih1);

    anorm_kernel<<<1, 256>>>(w_h1h1, w_h2h2, mask, out);

    size_t smem = SMEM_FLOATS * sizeof(float);
    cudaFuncSetAttribute(scan_kernel,
                         cudaFuncAttributeMaxDynamicSharedMemorySize,
                         (int)smem);
    scan_kernel<<<BATCH / 2, NTHREADS_SCAN, smem>>>(
        mask, w_h1h1, b_h1h1, w_h1h2, b_h1h2, w_h2h2, b_h2h2,
        w_h2o, b_h2o, tau_adp_h1, tau_adp_h2, tau_m_h1, tau_m_h2,
        tau_m_o, hid1_mem0, hid2_mem0, out_mem0, out);
}